// round 4
// baseline (speedup 1.0000x reference)
#include <cuda_runtime.h>

typedef unsigned long long u64;
typedef unsigned int u32;

#define NA 8192
#define NB 8192
#define NLAYERS 16

#define RP_ROWS 16
#define RP_THREADS 512
#define RP_BLOCKS (NA / RP_ROWS)       // 512

#define CP_THREADS 128
#define CP_COLS (CP_THREADS * 16)      // 2048 cols per block
#define CP_GX (NB / CP_COLS)           // 4
#define CP_CHUNK 128                   // rows per chunk
#define CP_GY (NA / CP_CHUNK)          // 64

// ---------------- static device scratch (no allocation) ----------------
__device__ __align__(128) unsigned char d_M[(size_t)NA * NB];  // 64 MB uf8
__device__ float d_u[NA];
__device__ float d_v[NB];
__device__ __align__(16) float d_part[(size_t)CP_GY * NB];
__device__ int d_ctr[CP_GX];  // zero-init; self-resetting each layer

// ---------------- packed f32x2 helpers ----------------
__device__ __forceinline__ u64 fma2(u64 a, u64 b, u64 c) {
    u64 d;
    asm("fma.rn.f32x2 %0,%1,%2,%3;" : "=l"(d) : "l"(a), "l"(b), "l"(c));
    return d;
}
__device__ __forceinline__ u64 add2(u64 a, u64 b) {
    u64 d;
    asm("add.rn.f32x2 %0,%1,%2;" : "=l"(d) : "l"(a), "l"(b));
    return d;
}
__device__ __forceinline__ u64 mul2(u64 a, u64 b) {
    u64 d;
    asm("mul.rn.f32x2 %0,%1,%2;" : "=l"(d) : "l"(a), "l"(b));
    return d;
}
__device__ __forceinline__ u64 pack2(float x) {
    u64 d;
    asm("mov.b64 %0, {%1, %1};" : "=l"(d) : "f"(x));
    return d;
}

#define MAG2  0x4B4000004B400000ull   //  12582912.0f x2
#define NMAG2 0xCB400000CB400000ull   // -12582912.0f x2
#define NONE2 0xBF800000BF800000ull   // -1.0f x2

// exp2 poly coefficients (packed)
struct EC { u64 p5, p4, p3, p2, p1, p0; };
__device__ __forceinline__ EC make_ec() {
    EC e;
    e.p5 = pack2(1.33335581465e-3f);
    e.p4 = pack2(9.61812910763e-3f);
    e.p3 = pack2(5.55041086648e-2f);
    e.p2 = pack2(2.40226506959e-1f);
    e.p1 = pack2(6.93147180560e-1f);
    e.p0 = pack2(1.0f);
    return e;
}

// ---------------- uf8 codec ----------------
// decode pair: bytes k,k+1 of w -> packed fp32 pair {2^(b>>4-15)*(1+(b&15)/16)}
// bits = (byte<<19) + 0x38000000, built as PRMT(byte->bits16..23) then *8+const.
__device__ __forceinline__ u64 dec2(u32 w, u32 sel0, u32 sel1) {
    u64 d;
    asm("{\n\t"
        ".reg .b32 lo, hi;\n\t"
        "prmt.b32 lo, %1, 0, %2;\n\t"
        "prmt.b32 hi, %1, 0, %3;\n\t"
        "mad.lo.u32 lo, lo, 8, 0x38000000;\n\t"
        "mad.lo.u32 hi, hi, 8, 0x38000000;\n\t"
        "mov.b64 %0, {lo, hi};\n\t"
        "}" : "=l"(d) : "r"(w), "r"(sel0), "r"(sel1));
    return d;
}

// encode a packed pair of C values -> two uf8 bytes (b0 | b1<<8), MUFU-free.
// y = 2^(c*negk); byte = (ybits + 0x40000 - 0x38000000) >> 19.
__device__ __forceinline__ u32 enc2(u64 cpair, u64 negk2, const EC& ec) {
    u64 p = mul2(cpair, negk2);
    u64 t = add2(p, MAG2);
    u64 uu = add2(t, NMAG2);
    u64 fr = fma2(uu, NONE2, p);
    u64 r = fma2(ec.p5, fr, ec.p4);
    r = fma2(r, fr, ec.p3);
    r = fma2(r, fr, ec.p2);
    r = fma2(r, fr, ec.p1);
    r = fma2(r, fr, ec.p0);
    u32 tl = (u32)t, th = (u32)(t >> 32);
    u32 rl = (u32)r, rh = (u32)(r >> 32);
    u32 b0 = ((tl << 23) + rl + 0xC8040000u) >> 19;
    u32 b1 = ((th << 23) + rh + 0xC8040000u) >> 19;
    return b0 | (b1 << 8);
}

// ---------------- encode M = exp(-C/eps) to uf8; init v = 1 ----------------
__global__ void __launch_bounds__(256) encode_kernel(const float* __restrict__ C,
                                                     const float* __restrict__ epsp) {
    const float eps = __ldg(epsp);
    const u64 negk2 = pack2(-1.0f / (eps * 0.69314718056f));
    const EC ec = make_ec();
    size_t idx = (size_t)blockIdx.x * 256 + threadIdx.x;  // one per 8 elements
    if (idx < NB) d_v[idx] = 1.0f;
    const ulonglong2* Cp = (const ulonglong2*)C;
    ulonglong2 cA = Cp[idx * 2 + 0];   // floats 0..3
    ulonglong2 cB = Cp[idx * 2 + 1];   // floats 4..7
    u32 lo = enc2(cA.x, negk2, ec) | (enc2(cA.y, negk2, ec) << 16);
    u32 hi = enc2(cB.x, negk2, ec) | (enc2(cB.y, negk2, ec) << 16);
    ((uint2*)d_M)[idx] = make_uint2(lo, hi);
}

// ---------------- row pass: u_i = alpha_i / sum_j M_ij v_j ----------------
__global__ void __launch_bounds__(RP_THREADS) row_pass(const float* __restrict__ alpha) {
    const int t = threadIdx.x;
    const int i0 = blockIdx.x * RP_ROWS;

    // this thread's 16 v values (cols 16t..16t+15) as 8 packed pairs
    const ulonglong2* vp = (const ulonglong2*)d_v;
    u64 vr[8];
#pragma unroll
    for (int q = 0; q < 4; ++q) {
        ulonglong2 vv = vp[t * 4 + q];
        vr[q * 2 + 0] = vv.x;
        vr[q * 2 + 1] = vv.y;
    }

    u64 acc[RP_ROWS];
#pragma unroll
    for (int r = 0; r < RP_ROWS; ++r) acc[r] = 0;

    const uint4* Mp = (const uint4*)d_M;
    size_t base = (size_t)i0 * (NB / 16) + t;

#pragma unroll 4
    for (int r = 0; r < RP_ROWS; ++r) {
        uint4 m = Mp[base + (size_t)r * (NB / 16)];
        u64 a = acc[r];
        a = fma2(dec2(m.x, 0x4044, 0x4144), vr[0], a);
        a = fma2(dec2(m.x, 0x4244, 0x4344), vr[1], a);
        a = fma2(dec2(m.y, 0x4044, 0x4144), vr[2], a);
        a = fma2(dec2(m.y, 0x4244, 0x4344), vr[3], a);
        a = fma2(dec2(m.z, 0x4044, 0x4144), vr[4], a);
        a = fma2(dec2(m.z, 0x4244, 0x4344), vr[5], a);
        a = fma2(dec2(m.w, 0x4044, 0x4144), vr[6], a);
        a = fma2(dec2(m.w, 0x4244, 0x4344), vr[7], a);
        acc[r] = a;
    }

    // cross-thread reduction: 8 rows at a time through smem
    __shared__ float sred[8][RP_THREADS];
    __shared__ float sfin[8][2];
#pragma unroll
    for (int g = 0; g < RP_ROWS / 8; ++g) {
        __syncthreads();
#pragma unroll
        for (int rr = 0; rr < 8; ++rr) {
            u64 a = acc[g * 8 + rr];
            sred[rr][t] = __uint_as_float((u32)a) + __uint_as_float((u32)(a >> 32));
        }
        __syncthreads();
        int rr = t >> 6;   // 0..7
        int b = t & 63;
        float s = 0.0f;
#pragma unroll
        for (int k = 0; k < 8; ++k) s += sred[rr][b + 64 * k];
#pragma unroll
        for (int o = 16; o > 0; o >>= 1) s += __shfl_down_sync(0xffffffffu, s, o);
        if ((t & 31) == 0) sfin[rr][b >> 5] = s;
        __syncthreads();
        if (t < 8) {
            int row = i0 + g * 8 + t;
            d_u[row] = alpha[row] / (sfin[t][0] + sfin[t][1]);
        }
    }
}

// ---------------- col pass + fused combine ----------------
// part[chunk][j] = sum_{i in chunk} M_ij u_i ; last block per column group
// sums all chunks and writes v_j = beta_j / s_j.
__global__ void __launch_bounds__(CP_THREADS) col_pass(const float* __restrict__ beta) {
    const int t = threadIdx.x;
    const int i0 = blockIdx.y * CP_CHUNK;
    const int j16 = blockIdx.x * CP_THREADS + t;  // uint4 index within a row

    const uint4* Mp = (const uint4*)d_M;
    size_t base = (size_t)i0 * (NB / 16) + j16;

    u64 a[8];
#pragma unroll
    for (int k = 0; k < 8; ++k) a[k] = 0;

#pragma unroll 4
    for (int r = 0; r < CP_CHUNK; ++r) {
        uint4 m = Mp[base + (size_t)r * (NB / 16)];
        u64 u2 = pack2(__ldg(&d_u[i0 + r]));
        a[0] = fma2(dec2(m.x, 0x4044, 0x4144), u2, a[0]);
        a[1] = fma2(dec2(m.x, 0x4244, 0x4344), u2, a[1]);
        a[2] = fma2(dec2(m.y, 0x4044, 0x4144), u2, a[2]);
        a[3] = fma2(dec2(m.y, 0x4244, 0x4344), u2, a[3]);
        a[4] = fma2(dec2(m.z, 0x4044, 0x4144), u2, a[4]);
        a[5] = fma2(dec2(m.z, 0x4244, 0x4344), u2, a[5]);
        a[6] = fma2(dec2(m.w, 0x4044, 0x4144), u2, a[6]);
        a[7] = fma2(dec2(m.w, 0x4244, 0x4344), u2, a[7]);
    }

    // store this chunk's partials (16 consecutive floats per thread)
    {
        ulonglong2* P = (ulonglong2*)(d_part + (size_t)blockIdx.y * NB + (size_t)j16 * 16);
        P[0] = make_ulonglong2(a[0], a[1]);
        P[1] = make_ulonglong2(a[2], a[3]);
        P[2] = make_ulonglong2(a[4], a[5]);
        P[3] = make_ulonglong2(a[6], a[7]);
    }

    // last-block-done combine for this column group
    __threadfence();
    __shared__ int isLast;
    if (t == 0) {
        int old = atomicAdd(&d_ctr[blockIdx.x], 1);
        isLast = (old == CP_GY - 1);
    }
    __syncthreads();
    if (isLast) {
        int j0 = blockIdx.x * CP_COLS + t * 16;
        float4 s0 = make_float4(0, 0, 0, 0), s1 = s0, s2 = s0, s3 = s0;
#pragma unroll 8
        for (int c = 0; c < CP_GY; ++c) {
            const float4* P = (const float4*)(d_part + (size_t)c * NB + j0);
            float4 p0 = P[0], p1 = P[1], p2 = P[2], p3 = P[3];
            s0.x += p0.x; s0.y += p0.y; s0.z += p0.z; s0.w += p0.w;
            s1.x += p1.x; s1.y += p1.y; s1.z += p1.z; s1.w += p1.w;
            s2.x += p2.x; s2.y += p2.y; s2.z += p2.z; s2.w += p2.w;
            s3.x += p3.x; s3.y += p3.y; s3.z += p3.z; s3.w += p3.w;
        }
        const float4* B = (const float4*)(beta + j0);
        float4 b0 = B[0], b1 = B[1], b2 = B[2], b3 = B[3];
        float4* V = (float4*)(d_v + j0);
        V[0] = make_float4(b0.x / s0.x, b0.y / s0.y, b0.z / s0.z, b0.w / s0.w);
        V[1] = make_float4(b1.x / s1.x, b1.y / s1.y, b1.z / s1.z, b1.w / s1.w);
        V[2] = make_float4(b2.x / s2.x, b2.y / s2.y, b2.z / s2.z, b2.w / s2.w);
        V[3] = make_float4(b3.x / s3.x, b3.y / s3.y, b3.z / s3.z, b3.w / s3.w);
        if (t == 0) d_ctr[blockIdx.x] = 0;  // reset for next layer
    }
}

// ---------------- writeout: f = eps*ln u, g = eps*ln v ----------------
__global__ void __launch_bounds__(256) writeout_kernel(float* __restrict__ out, int n,
                                                       const float* __restrict__ epsp) {
    int i = blockIdx.x * 256 + threadIdx.x;
    float eps = __ldg(epsp);
    if (i < NA) {
        if (i < n) out[i] = eps * logf(d_u[i]);
    } else if (i < NA + NB) {
        if (i < n) out[i] = eps * logf(d_v[i - NA]);
    }
}

extern "C" void kernel_launch(void* const* d_in, const int* in_sizes, int n_in,
                              void* d_out, int out_size) {
    const float* alpha = (const float*)d_in[0];
    const float* beta  = (const float*)d_in[1];
    const float* C     = (const float*)d_in[2];
    const float* eps   = (const float*)d_in[3];

    encode_kernel<<<(int)(((size_t)NA * NB / 8) / 256), 256>>>(C, eps);
    for (int l = 0; l < NLAYERS; ++l) {
        row_pass<<<RP_BLOCKS, RP_THREADS>>>(alpha);
        col_pass<<<dim3(CP_GX, CP_GY), CP_THREADS>>>(beta);
    }
    writeout_kernel<<<(NA + NB + 255) / 256, 256>>>((float*)d_out, out_size, eps);
}

// round 5
// speedup vs baseline: 1.0788x; 1.0788x over previous
#include <cuda_runtime.h>

typedef unsigned long long u64;
typedef unsigned int u32;

#define NA 8192
#define NB 8192
#define NLAYERS 16

#define RP_ROWS 16
#define RP_THREADS 512
#define RP_BLOCKS (NA / RP_ROWS)       // 512

#define CP_THREADS 256
#define CP_COLS (CP_THREADS * 16)      // 4096 cols per block
#define CP_GX (NB / CP_COLS)           // 2
#define CP_CHUNK 128                   // rows per chunk
#define CP_GY (NA / CP_CHUNK)          // 64

// ---------------- static device scratch (no allocation) ----------------
__device__ __align__(128) unsigned char d_M[(size_t)NA * NB];  // 64 MB uf8
__device__ float d_u[NA];
__device__ float d_v[NB];
__device__ __align__(16) float d_part[(size_t)CP_GY * NB];
__device__ int d_ctr[CP_GX];  // zero-init; self-resetting each layer

// ---------------- packed f32x2 helpers (encode only) ----------------
__device__ __forceinline__ u64 fma2(u64 a, u64 b, u64 c) {
    u64 d;
    asm("fma.rn.f32x2 %0,%1,%2,%3;" : "=l"(d) : "l"(a), "l"(b), "l"(c));
    return d;
}
__device__ __forceinline__ u64 add2(u64 a, u64 b) {
    u64 d;
    asm("add.rn.f32x2 %0,%1,%2;" : "=l"(d) : "l"(a), "l"(b));
    return d;
}
__device__ __forceinline__ u64 mul2(u64 a, u64 b) {
    u64 d;
    asm("mul.rn.f32x2 %0,%1,%2;" : "=l"(d) : "l"(a), "l"(b));
    return d;
}
__device__ __forceinline__ u64 pack2(float x) {
    u64 d;
    asm("mov.b64 %0, {%1, %1};" : "=l"(d) : "f"(x));
    return d;
}

#define MAG2  0x4B4000004B400000ull   //  12582912.0f x2
#define NMAG2 0xCB400000CB400000ull   // -12582912.0f x2
#define NONE2 0xBF800000BF800000ull   // -1.0f x2

struct EC { u64 p5, p4, p3, p2, p1, p0; };
__device__ __forceinline__ EC make_ec() {
    EC e;
    e.p5 = pack2(1.33335581465e-3f);
    e.p4 = pack2(9.61812910763e-3f);
    e.p3 = pack2(5.55041086648e-2f);
    e.p2 = pack2(2.40226506959e-1f);
    e.p1 = pack2(6.93147180560e-1f);
    e.p0 = pack2(1.0f);
    return e;
}

// ---------------- uf8 codec ----------------
// decode: fp32 bits = (byte << 19) + 0x38000000
__device__ __forceinline__ float dec8(u32 w, int sh) {
    u32 b = (w >> (sh * 8)) & 0xFFu;
    return __uint_as_float((b << 19) + 0x38000000u);
}

// encode a packed pair of C values -> two uf8 bytes (b0 | b1<<8), MUFU-free.
__device__ __forceinline__ u32 enc2(u64 cpair, u64 negk2, const EC& ec) {
    u64 p = mul2(cpair, negk2);
    u64 t = add2(p, MAG2);
    u64 uu = add2(t, NMAG2);
    u64 fr = fma2(uu, NONE2, p);
    u64 r = fma2(ec.p5, fr, ec.p4);
    r = fma2(r, fr, ec.p3);
    r = fma2(r, fr, ec.p2);
    r = fma2(r, fr, ec.p1);
    r = fma2(r, fr, ec.p0);
    u32 tl = (u32)t, th = (u32)(t >> 32);
    u32 rl = (u32)r, rh = (u32)(r >> 32);
    u32 b0 = ((tl << 23) + rl + 0xC8040000u) >> 19;
    u32 b1 = ((th << 23) + rh + 0xC8040000u) >> 19;
    return b0 | (b1 << 8);
}

// ---------------- encode M = exp(-C/eps) to uf8; init v = 1 ----------------
__global__ void __launch_bounds__(256) encode_kernel(const float* __restrict__ C,
                                                     const float* __restrict__ epsp) {
    const float eps = __ldg(epsp);
    const u64 negk2 = pack2(-1.0f / (eps * 0.69314718056f));
    const EC ec = make_ec();
    size_t idx = (size_t)blockIdx.x * 256 + threadIdx.x;  // one per 8 elements
    if (idx < NB) d_v[idx] = 1.0f;
    const ulonglong2* Cp = (const ulonglong2*)C;
    ulonglong2 cA = Cp[idx * 2 + 0];
    ulonglong2 cB = Cp[idx * 2 + 1];
    u32 lo = enc2(cA.x, negk2, ec) | (enc2(cA.y, negk2, ec) << 16);
    u32 hi = enc2(cB.x, negk2, ec) | (enc2(cB.y, negk2, ec) << 16);
    ((uint2*)d_M)[idx] = make_uint2(lo, hi);
}

// ---------------- row pass: u_i = alpha_i / sum_j M_ij v_j ----------------
__global__ void __launch_bounds__(RP_THREADS) row_pass(const float* __restrict__ alpha) {
    const int t = threadIdx.x;
    const int i0 = blockIdx.x * RP_ROWS;

    const float4* vp = (const float4*)d_v;
    float4 va = vp[t * 4 + 0], vb = vp[t * 4 + 1], vc = vp[t * 4 + 2], vd = vp[t * 4 + 3];

    float acc[RP_ROWS];
#pragma unroll
    for (int r = 0; r < RP_ROWS; ++r) acc[r] = 0.0f;

    const uint4* Mp = (const uint4*)d_M;
    size_t base = (size_t)i0 * (NB / 16) + t;

#pragma unroll 4
    for (int r = 0; r < RP_ROWS; ++r) {
        uint4 m = Mp[base + (size_t)r * (NB / 16)];
        float s0 = dec8(m.x, 0) * va.x + dec8(m.x, 1) * va.y +
                   dec8(m.x, 2) * va.z + dec8(m.x, 3) * va.w;
        float s1 = dec8(m.y, 0) * vb.x + dec8(m.y, 1) * vb.y +
                   dec8(m.y, 2) * vb.z + dec8(m.y, 3) * vb.w;
        float s2 = dec8(m.z, 0) * vc.x + dec8(m.z, 1) * vc.y +
                   dec8(m.z, 2) * vc.z + dec8(m.z, 3) * vc.w;
        float s3 = dec8(m.w, 0) * vd.x + dec8(m.w, 1) * vd.y +
                   dec8(m.w, 2) * vd.z + dec8(m.w, 3) * vd.w;
        acc[r] = (s0 + s1) + (s2 + s3);
    }

    __shared__ float sred[8][RP_THREADS];
    __shared__ float sfin[8][2];
#pragma unroll
    for (int g = 0; g < RP_ROWS / 8; ++g) {
        __syncthreads();
#pragma unroll
        for (int rr = 0; rr < 8; ++rr) sred[rr][t] = acc[g * 8 + rr];
        __syncthreads();
        int rr = t >> 6;
        int b = t & 63;
        float s = 0.0f;
#pragma unroll
        for (int k = 0; k < 8; ++k) s += sred[rr][b + 64 * k];
#pragma unroll
        for (int o = 16; o > 0; o >>= 1) s += __shfl_down_sync(0xffffffffu, s, o);
        if ((t & 31) == 0) sfin[rr][b >> 5] = s;
        __syncthreads();
        if (t < 8) {
            int row = i0 + g * 8 + t;
            d_u[row] = alpha[row] / (sfin[t][0] + sfin[t][1]);
        }
    }
}

// ---------------- col pass + fused combine ----------------
__global__ void __launch_bounds__(CP_THREADS) col_pass(const float* __restrict__ beta) {
    const int t = threadIdx.x;
    const int i0 = blockIdx.y * CP_CHUNK;
    const int j16 = blockIdx.x * CP_THREADS + t;

    const uint4* Mp = (const uint4*)d_M;
    size_t base = (size_t)i0 * (NB / 16) + j16;

    float a[16];
#pragma unroll
    for (int k = 0; k < 16; ++k) a[k] = 0.0f;

#pragma unroll 4
    for (int r = 0; r < CP_CHUNK; ++r) {
        uint4 m = Mp[base + (size_t)r * (NB / 16)];
        float ui = __ldg(&d_u[i0 + r]);
        a[0] += dec8(m.x, 0) * ui;  a[1] += dec8(m.x, 1) * ui;
        a[2] += dec8(m.x, 2) * ui;  a[3] += dec8(m.x, 3) * ui;
        a[4] += dec8(m.y, 0) * ui;  a[5] += dec8(m.y, 1) * ui;
        a[6] += dec8(m.y, 2) * ui;  a[7] += dec8(m.y, 3) * ui;
        a[8] += dec8(m.z, 0) * ui;  a[9] += dec8(m.z, 1) * ui;
        a[10] += dec8(m.z, 2) * ui; a[11] += dec8(m.z, 3) * ui;
        a[12] += dec8(m.w, 0) * ui; a[13] += dec8(m.w, 1) * ui;
        a[14] += dec8(m.w, 2) * ui; a[15] += dec8(m.w, 3) * ui;
    }

    {
        float4* P = (float4*)(d_part + (size_t)blockIdx.y * NB + (size_t)j16 * 16);
        P[0] = make_float4(a[0], a[1], a[2], a[3]);
        P[1] = make_float4(a[4], a[5], a[6], a[7]);
        P[2] = make_float4(a[8], a[9], a[10], a[11]);
        P[3] = make_float4(a[12], a[13], a[14], a[15]);
    }

    // last-block-done combine for this column group
    __threadfence();
    __shared__ int isLast;
    if (t == 0) {
        int old = atomicAdd(&d_ctr[blockIdx.x], 1);
        isLast = (old == CP_GY - 1);
    }
    __syncthreads();
    if (isLast) {
        int j0 = blockIdx.x * CP_COLS + t * 16;
        float4 s0 = make_float4(0, 0, 0, 0), s1 = s0, s2 = s0, s3 = s0;
#pragma unroll 8
        for (int c = 0; c < CP_GY; ++c) {
            const float4* P = (const float4*)(d_part + (size_t)c * NB + j0);
            float4 p0 = P[0], p1 = P[1], p2 = P[2], p3 = P[3];
            s0.x += p0.x; s0.y += p0.y; s0.z += p0.z; s0.w += p0.w;
            s1.x += p1.x; s1.y += p1.y; s1.z += p1.z; s1.w += p1.w;
            s2.x += p2.x; s2.y += p2.y; s2.z += p2.z; s2.w += p2.w;
            s3.x += p3.x; s3.y += p3.y; s3.z += p3.z; s3.w += p3.w;
        }
        const float4* B = (const float4*)(beta + j0);
        float4 b0 = B[0], b1 = B[1], b2 = B[2], b3 = B[3];
        float4* V = (float4*)(d_v + j0);
        V[0] = make_float4(b0.x / s0.x, b0.y / s0.y, b0.z / s0.z, b0.w / s0.w);
        V[1] = make_float4(b1.x / s1.x, b1.y / s1.y, b1.z / s1.z, b1.w / s1.w);
        V[2] = make_float4(b2.x / s2.x, b2.y / s2.y, b2.z / s2.z, b2.w / s2.w);
        V[3] = make_float4(b3.x / s3.x, b3.y / s3.y, b3.z / s3.z, b3.w / s3.w);
        if (t == 0) d_ctr[blockIdx.x] = 0;  // reset for next layer
    }
}

// ---------------- writeout: f = eps*ln u, g = eps*ln v ----------------
__global__ void __launch_bounds__(256) writeout_kernel(float* __restrict__ out, int n,
                                                       const float* __restrict__ epsp) {
    int i = blockIdx.x * 256 + threadIdx.x;
    float eps = __ldg(epsp);
    if (i < NA) {
        if (i < n) out[i] = eps * logf(d_u[i]);
    } else if (i < NA + NB) {
        if (i < n) out[i] = eps * logf(d_v[i - NA]);
    }
}

extern "C" void kernel_launch(void* const* d_in, const int* in_sizes, int n_in,
                              void* d_out, int out_size) {
    const float* alpha = (const float*)d_in[0];
    const float* beta  = (const float*)d_in[1];
    const float* C     = (const float*)d_in[2];
    const float* eps   = (const float*)d_in[3];

    encode_kernel<<<(int)(((size_t)NA * NB / 8) / 256), 256>>>(C, eps);
    for (int l = 0; l < NLAYERS; ++l) {
        row_pass<<<RP_BLOCKS, RP_THREADS>>>(alpha);
        col_pass<<<dim3(CP_GX, CP_GY), CP_THREADS>>>(beta);
    }
    writeout_kernel<<<(NA + NB + 255) / 256, 256>>>((float*)d_out, out_size, eps);
}